// round 11
// baseline (speedup 1.0000x reference)
#include <cuda_runtime.h>
#include <cuda_fp16.h>
#include <cstdint>

typedef unsigned long long ull;

#define NROWS 147584
#define KSIZE 147456
#define LATD  512
#define NB    16
#define NFIN  128
#define NFOUT 128
#define HH    64
#define WW    64

// split-fp16 weights, k-reordered: k' = tap*128 + fi
__device__ __align__(16) __half g_kh[NB * KSIZE];   // 4.72 MB
__device__ __align__(16) __half g_kl[NB * KSIZE];   // 4.72 MB
__device__ float g_bias[NB * NFOUT];

// ---------------- f32x2 helpers ----------------
#define PK2(dst, a, b) \
  asm("mov.b64 %0, {%1, %2};" : "=l"(dst) : "r"(__float_as_uint(a)), "r"(__float_as_uint(b)))
#define FMA2(acc, a, b) \
  asm("fma.rn.f32x2 %0, %1, %2, %3;" : "=l"(acc) : "l"(a), "l"(b), "l"(acc))

// ---------------- cp.async ----------------
#define CPA16(dst, src) \
  asm volatile("cp.async.cg.shared.global [%0], [%1], 16;" :: "r"(dst), "l"(src))
#define CPCOMMIT() asm volatile("cp.async.commit_group;" ::: "memory")
#define CPWAIT2()  asm volatile("cp.async.wait_group 2;" ::: "memory")
#define CPWAIT1()  asm volatile("cp.async.wait_group 1;" ::: "memory")
#define CPWAIT0()  asm volatile("cp.async.wait_group 0;" ::: "memory")

__device__ __forceinline__ uint32_t smem_u32(const void* p) {
  uint32_t a;
  asm("{ .reg .u64 t; cvta.to.shared.u64 t, %1; cvt.u32.u64 %0, t; }" : "=r"(a) : "l"(p));
  return a;
}

// ---------------- warp-MMA helpers ----------------
#define LDSM4(r0, r1, r2, r3, addr) \
  asm volatile("ldmatrix.sync.aligned.m8n8.x4.shared.b16 {%0,%1,%2,%3}, [%4];" \
               : "=r"(r0), "=r"(r1), "=r"(r2), "=r"(r3) : "r"(addr))
#define MMA16816(c, a, b0, b1) \
  asm volatile("mma.sync.aligned.m16n8k16.row.col.f32.f16.f16.f32 " \
               "{%0,%1,%2,%3}, {%4,%5,%6,%7}, {%8,%9}, {%0,%1,%2,%3};" \
               : "+f"((c)[0]), "+f"((c)[1]), "+f"((c)[2]), "+f"((c)[3]) \
               : "r"((a)[0]), "r"((a)[1]), "r"((a)[2]), "r"((a)[3]), \
                 "r"(b0), "r"(b1))

// ===========================================================================
// Kernel A: hyper GEMM. 256 rows/block, 1 row/thread, 4 smem buffers,
// 3 chunks in flight (cp.async wait_group 2), ONE sync per chunk.
// lat transposed [k][16b] in smem; 4x LDS.128 broadcast serves 8 FFMA2.
// Epilogue: split-fp16 weights in k' = tap*128+fi order + f32 bias.
// ===========================================================================
#define HKC   16
#define HRS   20                               // row stride (floats)
#define HROWS 256
#define HBUF  (HROWS * HRS)                    // 5120 floats / buffer
#define NCHK  (LATD / HKC)                     // 32
#define HSMEM ((4 * HBUF + LATD * 16) * 4)     // 81920 + 32768 = 114688 B

__global__ __launch_bounds__(256) void hyper_gemm(
    const float* __restrict__ lat, const float* __restrict__ Wm,
    const float* __restrict__ bias)
{
  extern __shared__ __align__(16) float hsm[];
  float* Ws = hsm;                     // [4][256][20]
  float* latc = hsm + 4 * HBUF;        // [512][16]
  const uint32_t wsb = smem_u32(Ws);
  const int tid = threadIdx.x;
  const int j0 = blockIdx.x * HROWS;
  const int j = j0 + tid;

  ull acc[8];
#pragma unroll
  for (int i = 0; i < 8; i++) acc[i] = 0ull;

  for (int idx = tid; idx < LATD * 16; idx += 256)
    latc[idx] = lat[(idx & 15) * LATD + (idx >> 4)];

  // prologue: chunks 0..2 -> bufs 0..2   (4 float4 per thread per chunk)
#pragma unroll
  for (int c0 = 0; c0 < 3; c0++) {
#pragma unroll
    for (int p = 0; p < 4; p++) {
      int idx = p * 256 + tid;
      int r = idx >> 2, q = idx & 3;
      if (j0 + r < NROWS)
        CPA16(wsb + (uint32_t)(c0 * HBUF + r * HRS + q * 4) * 4,
              Wm + (size_t)(j0 + r) * LATD + c0 * HKC + q * 4);
    }
    CPCOMMIT();
  }

  for (int c = 0; c < NCHK; c++) {
    CPWAIT2();            // chunk c landed
    __syncthreads();      // collective visibility; buf (c+3)&3 free
    if (c + 3 < NCHK) {
#pragma unroll
      for (int p = 0; p < 4; p++) {
        int idx = p * 256 + tid;
        int r = idx >> 2, q = idx & 3;
        if (j0 + r < NROWS)
          CPA16(wsb + (uint32_t)(((c + 3) & 3) * HBUF + r * HRS + q * 4) * 4,
                Wm + (size_t)(j0 + r) * LATD + (c + 3) * HKC + q * 4);
      }
      CPCOMMIT();
    }
    const ulonglong2* latp = reinterpret_cast<const ulonglong2*>(latc);
    const float* wr = &Ws[(c & 3) * HBUF + tid * HRS];
#pragma unroll
    for (int k = 0; k < HKC; k++) {
      float wv = wr[k];
      ull w2; PK2(w2, wv, wv);
      int kk = c * HKC + k;
#pragma unroll
      for (int q = 0; q < 4; q++) {
        ulonglong2 lv = latp[kk * 4 + q];
        FMA2(acc[2 * q + 0], w2, lv.x);
        FMA2(acc[2 * q + 1], w2, lv.y);
      }
    }
  }

  if (j < KSIZE) {
    int fo = j / 1152;
    int rem = j - fo * 1152;
    int fi = rem / 9;
    int tap = rem - fi * 9;
    size_t dst = (size_t)fo * 1152 + tap * 128 + fi;
    float bv = bias[j];
#pragma unroll
    for (int p = 0; p < 8; p++) {
      float2 v = *reinterpret_cast<float2*>(&acc[p]);
      float va = v.x + bv, vb = v.y + bv;
      __half ha = __float2half(va);
      __half la = __float2half(va - __half2float(ha));
      __half hb = __float2half(vb);
      __half lb = __float2half(vb - __half2float(hb));
      g_kh[(size_t)(2 * p + 0) * KSIZE + dst] = ha;
      g_kl[(size_t)(2 * p + 0) * KSIZE + dst] = la;
      g_kh[(size_t)(2 * p + 1) * KSIZE + dst] = hb;
      g_kl[(size_t)(2 * p + 1) * KSIZE + dst] = lb;
    }
  } else if (j < NROWS) {
    int fo = j - KSIZE;
    float bv = bias[j];
#pragma unroll
    for (int p = 0; p < 8; p++) {
      float2 v = *reinterpret_cast<float2*>(&acc[p]);
      g_bias[(2 * p + 0) * NFOUT + fo] = v.x + bv;
      g_bias[(2 * p + 1) * NFOUT + fo] = v.y + bv;
    }
  }
}

// ===========================================================================
// Kernel B: warp-MMA fp16 2-pass implicit-GEMM conv, PIPELINED tap-group
// staging. Steps s=0..23: (fc = s/3, tap-row g = s%3). Per step, A for
// taps {3g..3g+2} (hi+lo, 24.6KB) double-buffered via cp.async: issue s+1,
// wait_group 1 -> copy lands during the 96-MMA/warp compute window.
// x tile double-buffered per fc; staged mid-fc overlapping compute.
// A rows XOR-swizzled 32B: off = r*32 + ((ch*16) ^ ((r&4)<<2)).
// ===========================================================================
#define CS    36                      // bytes per x cell (16 fp16 + 4 pad)
#define XTB   (272 * CS)              // 9792 B per x buffer
#define ATILE 4096                    // one (tap,hl) tile: 128 rows * 32 B
#define ASTEP (6 * ATILE)             // 24576 B per step buffer
#define X_OFF (2 * ASTEP)             // 49152
#define BIAS_OFF (X_OFF + 2 * XTB)    // 68736
#define CONV_SMEM (BIAS_OFF + NFOUT * 4)   // 69248 B

__device__ __forceinline__ void conv_issue_A(
    uint32_t sab, const __half* kh, const __half* kl,
    int fc, int g, int bufofs, int tid)
{
  const int kofs = fc * 16;
#pragma unroll
  for (int p = 0; p < 6; p++) {
    int i = p * 256 + tid;
    int tile = i >> 8;                 // tl*2 + hl
    int rem = i & 255;
    int r = rem >> 1, ch = rem & 1;
    int tl = tile >> 1, hl = tile & 1;
    const __half* src = (hl ? kl : kh) + (size_t)r * 1152 + (3 * g + tl) * 128 + kofs + ch * 8;
    uint32_t dst = (uint32_t)(bufofs + tile * ATILE + r * 32 + ((ch << 4) ^ ((r & 4) << 2)));
    CPA16(sab + dst, src);
  }
  CPCOMMIT();
}

__device__ __forceinline__ void conv_stage_x(
    unsigned char* sxt, const float* xb, int fc, int t, int tid)
{
  const int fib = fc * 16;
#pragma unroll
  for (int p = 0; p < 17; p++) {
    int i = p * 256 + tid;
    int fi = i / 272, cell = i - fi * 272;
    int r = cell / 68, c = cell - r * 68;
    int gr = 2 * t + r;                // padded row
    float v = 0.f;
    if ((unsigned)(gr - 1) < (unsigned)HH && (unsigned)(c - 1) < (unsigned)WW)
      v = xb[(size_t)(fib + fi) * (HH * WW) + (gr - 1) * WW + (c - 1)];
    *reinterpret_cast<__half*>(sxt + cell * CS + fi * 2) = __float2half(v);
  }
}

__global__ __launch_bounds__(256, 2) void conv_mma(
    const float* __restrict__ x, float* __restrict__ out)
{
  extern __shared__ __align__(16) unsigned char sm[];
  float* sbias = reinterpret_cast<float*>(sm + BIAS_OFF);

  const int tid = threadIdx.x;
  const int lane = tid & 31, wid = tid >> 5;
  const int wm = wid >> 2;          // m-half (64 fouts)
  const int wn = wid & 3;           // n-quarter (32 px)
  const int t = blockIdx.x;         // out rows 2t, 2t+1
  const int b = blockIdx.y;

  float acc[4][4][4];
#pragma unroll
  for (int f = 0; f < 4; f++)
#pragma unroll
    for (int j = 0; j < 4; j++)
#pragma unroll
      for (int q = 0; q < 4; q++) acc[f][j][q] = 0.f;

  if (tid < NFOUT) sbias[tid] = g_bias[b * NFOUT + tid];

  const __half* kh = g_kh + (size_t)b * KSIZE;
  const __half* kl = g_kl + (size_t)b * KSIZE;
  const float* xb = x + (size_t)(b * NFIN) * (HH * WW);

  const uint32_t sab = smem_u32(sm);
  const uint32_t aRowBase =
      (uint32_t)((wm * 64 + (lane & 15)) * 32) +
      ((uint32_t)((lane >> 4) << 4) ^ (uint32_t)((lane & 4) << 2));

  int pj[4];
#pragma unroll
  for (int j = 0; j < 4; j++) {
    int px = wn * 32 + j * 8 + (lane >> 2);
    pj[j] = (px >> 6) * 68 + (px & 63);
  }
  const uint32_t bOff = (uint32_t)((lane & 3) * 4);

  // prologue: x(0) and A(step 0)
  conv_stage_x(sm + X_OFF, xb, 0, t, tid);
  conv_issue_A(sab, kh, kl, 0, 0, 0, tid);

  for (int s = 0; s < 24; s++) {
    const int fc = s / 3, g = s - 3 * fc;
    __syncthreads();                   // all warps done compute(s-1); x stores drained
    if (s + 1 < 24) {
      int s1 = s + 1, fc1 = s1 / 3, g1 = s1 - 3 * fc1;
      conv_issue_A(sab, kh, kl, fc1, g1, (s1 & 1) * ASTEP, tid);
      CPWAIT1();                       // A(s) landed; A(s+1) in flight
    } else {
      CPWAIT0();
    }
    __syncthreads();                   // A(s) + x(fc) visible to all warps

    // stage x(fc+1) mid-fc: overlaps this step's compute per-warp
    if (g == 1 && fc + 1 < 8)
      conv_stage_x(sm + X_OFF + ((fc + 1) & 1) * XTB, xb, fc + 1, t, tid);

    unsigned char* sxt = sm + X_OFF + (fc & 1) * XTB;
    const uint32_t abase = sab + (uint32_t)((s & 1) * ASTEP) + aRowBase;
#pragma unroll
    for (int tl = 0; tl < 3; tl++) {
      const int off = g * 68 + tl;     // tap = g*3+tl -> dy=g, dx=tl
      uint32_t bfr[8];
#pragma unroll
      for (int j = 0; j < 4; j++) {
        uint32_t ca = (uint32_t)((pj[j] + off) * CS) + bOff;
        bfr[2 * j]     = *reinterpret_cast<const uint32_t*>(sxt + ca);
        bfr[2 * j + 1] = *reinterpret_cast<const uint32_t*>(sxt + ca + 16);
      }
      const uint32_t tileH = abase + (uint32_t)(tl * 2 * ATILE);
      uint32_t a[4][4];
#pragma unroll
      for (int f = 0; f < 4; f++)
        LDSM4(a[f][0], a[f][1], a[f][2], a[f][3], tileH + (uint32_t)(f * 512));
#pragma unroll
      for (int f = 0; f < 4; f++)
#pragma unroll
        for (int j = 0; j < 4; j++)
          MMA16816(acc[f][j], a[f], bfr[2 * j], bfr[2 * j + 1]);
#pragma unroll
      for (int f = 0; f < 4; f++)
        LDSM4(a[f][0], a[f][1], a[f][2], a[f][3], tileH + (uint32_t)(ATILE + f * 512));
#pragma unroll
      for (int f = 0; f < 4; f++)
#pragma unroll
        for (int j = 0; j < 4; j++)
          MMA16816(acc[f][j], a[f], bfr[2 * j], bfr[2 * j + 1]);
    }
  }

  // ---- epilogue: bias + store ----
  float* ob = out + (size_t)b * (NFOUT * HH * WW) + t * 128;
#pragma unroll
  for (int f = 0; f < 4; f++) {
    int fo0 = wm * 64 + f * 16 + (lane >> 2);
    float bv0 = sbias[fo0], bv1 = sbias[fo0 + 8];
#pragma unroll
    for (int j = 0; j < 4; j++) {
      int n = wn * 32 + j * 8 + 2 * (lane & 3);
      float2 v0 = make_float2(acc[f][j][0] + bv0, acc[f][j][1] + bv0);
      float2 v1 = make_float2(acc[f][j][2] + bv1, acc[f][j][3] + bv1);
      *reinterpret_cast<float2*>(ob + (size_t)fo0 * (HH * WW) + n) = v0;
      *reinterpret_cast<float2*>(ob + (size_t)(fo0 + 8) * (HH * WW) + n) = v1;
    }
  }
}

// ===========================================================================
extern "C" void kernel_launch(void* const* d_in, const int* in_sizes, int n_in,
                              void* d_out, int out_size) {
  const float* x   = (const float*)d_in[0];
  const float* lat = (const float*)d_in[1];
  const float* Wm  = (const float*)d_in[2];
  const float* bv  = (const float*)d_in[3];
  float* out = (float*)d_out;

  cudaFuncSetAttribute(hyper_gemm, cudaFuncAttributeMaxDynamicSharedMemorySize, HSMEM);
  cudaFuncSetAttribute(conv_mma, cudaFuncAttributeMaxDynamicSharedMemorySize, CONV_SMEM);

  hyper_gemm<<<(NROWS + HROWS - 1) / HROWS, 256, HSMEM>>>(lat, Wm, bv);

  dim3 g(HH * WW / 128, NB);   // 32 x 16 = 512 CTAs
  conv_mma<<<g, 256, CONV_SMEM>>>(x, out);
}

// round 14
// speedup vs baseline: 1.0924x; 1.0924x over previous
#include <cuda_runtime.h>
#include <cuda_fp16.h>
#include <cstdint>

typedef unsigned long long ull;

#define NROWS 147584
#define KSIZE 147456
#define LATD  512
#define NB    16
#define NFIN  128
#define NFOUT 128
#define HH    64
#define WW    64

// split-fp16 weights, k-reordered: k' = tap*128 + fi
__device__ __align__(16) __half g_kh[NB * KSIZE];   // 4.72 MB
__device__ __align__(16) __half g_kl[NB * KSIZE];   // 4.72 MB
__device__ float g_bias[NB * NFOUT];

// ---------------- cp.async ----------------
#define CPA16(dst, src) \
  asm volatile("cp.async.cg.shared.global [%0], [%1], 16;" :: "r"(dst), "l"(src))
#define CPCOMMIT() asm volatile("cp.async.commit_group;" ::: "memory")
#define CPWAIT2()  asm volatile("cp.async.wait_group 2;" ::: "memory")
#define CPWAIT0()  asm volatile("cp.async.wait_group 0;" ::: "memory")

__device__ __forceinline__ uint32_t smem_u32(const void* p) {
  uint32_t a;
  asm("{ .reg .u64 t; cvta.to.shared.u64 t, %1; cvt.u32.u64 %0, t; }" : "=r"(a) : "l"(p));
  return a;
}

// ---------------- warp-MMA helpers ----------------
#define LDSM4(r0, r1, r2, r3, addr) \
  asm volatile("ldmatrix.sync.aligned.m8n8.x4.shared.b16 {%0,%1,%2,%3}, [%4];" \
               : "=r"(r0), "=r"(r1), "=r"(r2), "=r"(r3) : "r"(addr))
#define MMA16816(c, a, b0, b1) \
  asm volatile("mma.sync.aligned.m16n8k16.row.col.f32.f16.f16.f32 " \
               "{%0,%1,%2,%3}, {%4,%5,%6,%7}, {%8,%9}, {%0,%1,%2,%3};" \
               : "+f"((c)[0]), "+f"((c)[1]), "+f"((c)[2]), "+f"((c)[3]) \
               : "r"((a)[0]), "r"((a)[1]), "r"((a)[2]), "r"((a)[3]), \
                 "r"(b0), "r"(b1))
// tf32 MMA m16n8k8: D(16x8) += A(16x8) * B(8x8)
#define MMATF32(c, a0, a1, a2, a3, b0, b1) \
  asm volatile("mma.sync.aligned.m16n8k8.row.col.f32.tf32.tf32.f32 " \
               "{%0,%1,%2,%3}, {%4,%5,%6,%7}, {%8,%9}, {%0,%1,%2,%3};" \
               : "+f"((c)[0]), "+f"((c)[1]), "+f"((c)[2]), "+f"((c)[3]) \
               : "r"(a0), "r"(a1), "r"(a2), "r"(a3), "r"(b0), "r"(b1))
#define CVT_TF32(d, s) asm("cvt.rna.tf32.f32 %0, %1;" : "=r"(d) : "f"(s))

// ===========================================================================
// Kernel A: hyper GEMM on tensor cores (tf32, split 3-pass).
// D[16 batch, 256 rows] per CTA; A = lat (m16, split-tf32 in smem, per-chunk),
// B = W rows (f32 staged via cp.async, cvt to tf32 hi/lo on the fly).
// K chunks of 16 (2 ksteps of k8), FOUR W bufs, 2 chunks ahead (wait_group 2),
// 1 sync/chunk. (R12 bug: 3 bufs -> chunk c+3 landed on buf being read.)
// W_s stride 20 floats -> conflict-free B reads; lat_s stride 24 -> c-f A reads.
// Epilogue: split-fp16 weights in k' = tap*128+fi order + f32 bias.
// ===========================================================================
#define HKC   16
#define WST   20
#define WBUF  (256 * WST)                     // 5120 floats per buffer
#define LST   24
#define LBUF  (HKC * LST)                     // 384 floats per lat plane
#define NCHK  (LATD / HKC)                    // 32
// smem: W[4][WBUF] | latH[2][LBUF] | latL[2][LBUF]
#define HSMEM ((4 * WBUF + 4 * LBUF) * 4)     // 81920 + 6144 = 88064 B

__global__ __launch_bounds__(256) void hyper_gemm(
    const float* __restrict__ lat, const float* __restrict__ Wm,
    const float* __restrict__ bias)
{
  extern __shared__ __align__(16) float hsm[];
  float* Wsm = hsm;                        // [4][256][20]
  float* latH = hsm + 4 * WBUF;            // [2][16][24]
  float* latL = latH + 2 * LBUF;           // [2][16][24]
  const uint32_t wsb = smem_u32(Wsm);
  const int tid = threadIdx.x;
  const int lane = tid & 31, wid = tid >> 5;
  const int j0 = blockIdx.x * 256;
  const int gid = lane >> 2, tig = lane & 3;   // groupID, threadID-in-group

  float d[4][4];                            // 4 n-frags x 4 accs
#pragma unroll
  for (int f = 0; f < 4; f++)
#pragma unroll
    for (int q = 0; q < 4; q++) d[f][q] = 0.f;

  // stage lat chunk c into buf: 256 values, 1 per thread
  auto stage_lat = [&](int c, int buf) {
    int m = tid >> 4, k = tid & 15;
    float v = lat[m * LATD + c * HKC + k];
    uint32_t hb; CVT_TF32(hb, v);
    float hf = __uint_as_float(hb);
    uint32_t lb; CVT_TF32(lb, v - hf);
    latH[buf * LBUF + k * LST + m] = __uint_as_float(hb);
    latL[buf * LBUF + k * LST + m] = __uint_as_float(lb);
  };

  // prologue: W chunks 0..2 -> bufs 0..2; lat chunk 0 -> buf 0
#pragma unroll
  for (int c0 = 0; c0 < 3; c0++) {
#pragma unroll
    for (int p = 0; p < 4; p++) {
      int idx = p * 256 + tid;
      int r = idx >> 2, q = idx & 3;
      if (j0 + r < NROWS)
        CPA16(wsb + (uint32_t)(c0 * WBUF + r * WST + q * 4) * 4,
              Wm + (size_t)(j0 + r) * LATD + c0 * HKC + q * 4);
    }
    CPCOMMIT();
  }
  stage_lat(0, 0);

  for (int c = 0; c < NCHK; c++) {
    CPWAIT2();           // W(c) landed
    __syncthreads();     // visibility; compute(c-1) reads done -> buf (c+3)&3 free
    if (c + 3 < NCHK) {
#pragma unroll
      for (int p = 0; p < 4; p++) {
        int idx = p * 256 + tid;
        int r = idx >> 2, q = idx & 3;
        if (j0 + r < NROWS)
          CPA16(wsb + (uint32_t)(((c + 3) & 3) * WBUF + r * WST + q * 4) * 4,
                Wm + (size_t)(j0 + r) * LATD + (c + 3) * HKC + q * 4);
      }
      CPCOMMIT();
    }
    if (c + 1 < NCHK) stage_lat(c + 1, (c + 1) & 1);

    const float* wb = &Wsm[(c & 3) * WBUF];
    const float* lh = &latH[(c & 1) * LBUF];
    const float* ll = &latL[(c & 1) * LBUF];
#pragma unroll
    for (int ks = 0; ks < 2; ks++) {
      const int kk = ks * 8;
      // A fragments (m16k8): a0 (m=gid,k=tig) a1 (m+8,k) a2 (m,k+4) a3 (m+8,k+4)
      uint32_t ah0 = __float_as_uint(lh[(kk + tig) * LST + gid]);
      uint32_t ah1 = __float_as_uint(lh[(kk + tig) * LST + gid + 8]);
      uint32_t ah2 = __float_as_uint(lh[(kk + tig + 4) * LST + gid]);
      uint32_t ah3 = __float_as_uint(lh[(kk + tig + 4) * LST + gid + 8]);
      uint32_t al0 = __float_as_uint(ll[(kk + tig) * LST + gid]);
      uint32_t al1 = __float_as_uint(ll[(kk + tig) * LST + gid + 8]);
      uint32_t al2 = __float_as_uint(ll[(kk + tig + 4) * LST + gid]);
      uint32_t al3 = __float_as_uint(ll[(kk + tig + 4) * LST + gid + 8]);
#pragma unroll
      for (int f = 0; f < 4; f++) {
        // B frag (k8n8 col): b0 (k=tig, n=gid), b1 (k=tig+4, n=gid)
        const float* wr = wb + (wid * 32 + f * 8 + gid) * WST;
        float w0 = wr[kk + tig], w1 = wr[kk + tig + 4];
        uint32_t bh0, bh1, bl0, bl1;
        CVT_TF32(bh0, w0); CVT_TF32(bh1, w1);
        CVT_TF32(bl0, w0 - __uint_as_float(bh0));
        CVT_TF32(bl1, w1 - __uint_as_float(bh1));
        MMATF32(d[f], ah0, ah1, ah2, ah3, bh0, bh1);
        MMATF32(d[f], al0, al1, al2, al3, bh0, bh1);
        MMATF32(d[f], ah0, ah1, ah2, ah3, bl0, bl1);
      }
    }
  }

  // ---- epilogue: D[m][j] -> split-fp16 k-reordered scatter + bias ----
  // c0:(m=gid, n=2*tig) c1:(m, n+1) c2:(m+8, n) c3:(m+8, n+1)
#pragma unroll
  for (int f = 0; f < 4; f++) {
#pragma unroll
    for (int e = 0; e < 2; e++) {
      int j = j0 + wid * 32 + f * 8 + 2 * tig + e;
      float v0 = d[f][e];          // batch m = gid
      float v1 = d[f][2 + e];      // batch m = gid + 8
      if (j < KSIZE) {
        int fo = j / 1152;
        int rem = j - fo * 1152;
        int fi = rem / 9;
        int tap = rem - fi * 9;
        size_t dst = (size_t)fo * 1152 + tap * 128 + fi;
        float bv = bias[j];
        float va = v0 + bv, vb = v1 + bv;
        __half ha = __float2half(va);
        __half la = __float2half(va - __half2float(ha));
        __half hb = __float2half(vb);
        __half lb = __float2half(vb - __half2float(hb));
        g_kh[(size_t)gid * KSIZE + dst] = ha;
        g_kl[(size_t)gid * KSIZE + dst] = la;
        g_kh[(size_t)(gid + 8) * KSIZE + dst] = hb;
        g_kl[(size_t)(gid + 8) * KSIZE + dst] = lb;
      } else if (j < NROWS) {
        int fo = j - KSIZE;
        float bv = bias[j];
        g_bias[gid * NFOUT + fo] = v0 + bv;
        g_bias[(gid + 8) * NFOUT + fo] = v1 + bv;
      }
    }
  }
}

// ===========================================================================
// Kernel B: warp-MMA fp16 2-pass implicit-GEMM conv, 9-tap weight staging.
// (exact R10 structure - known 144.8us)
// ===========================================================================
#define CS   36                       // bytes per x cell (16 fp16 + 4 pad)
#define XTB  (272 * CS)               // 9792 B
#define ATILE 4096                    // one (tap,hl) tile: 128 rows * 32 B
#define A_ALL (18 * ATILE)            // 73728 B
#define X_OFF A_ALL
#define BIAS_OFF (A_ALL + XTB)
#define CONV_SMEM (BIAS_OFF + NFOUT * 4)   // 84032 B

__global__ __launch_bounds__(256, 2) void conv_mma(
    const float* __restrict__ x, float* __restrict__ out)
{
  extern __shared__ __align__(16) unsigned char sm[];
  unsigned char* sxt = sm + X_OFF;
  float* sbias = reinterpret_cast<float*>(sm + BIAS_OFF);

  const int tid = threadIdx.x;
  const int lane = tid & 31, wid = tid >> 5;
  const int wm = wid >> 2;          // m-half (64 fouts)
  const int wn = wid & 3;           // n-quarter (32 px)
  const int t = blockIdx.x;         // out rows 2t, 2t+1
  const int b = blockIdx.y;

  float acc[4][4][4];
#pragma unroll
  for (int f = 0; f < 4; f++)
#pragma unroll
    for (int j = 0; j < 4; j++)
#pragma unroll
      for (int q = 0; q < 4; q++) acc[f][j][q] = 0.f;

  if (tid < NFOUT) sbias[tid] = g_bias[b * NFOUT + tid];

  const __half* kh = g_kh + (size_t)b * KSIZE;
  const __half* kl = g_kl + (size_t)b * KSIZE;
  const float* xb = x + (size_t)(b * NFIN) * (HH * WW);

  const uint32_t sab = smem_u32(sm);
  const uint32_t aRowBase =
      (uint32_t)((wm * 64 + (lane & 15)) * 32) +
      ((uint32_t)((lane >> 4) << 4) ^ (uint32_t)((lane & 4) << 2));

  int pj[4];
#pragma unroll
  for (int j = 0; j < 4; j++) {
    int px = wn * 32 + j * 8 + (lane >> 2);
    pj[j] = (px >> 6) * 68 + (px & 63);
  }
  const uint32_t bOff = (uint32_t)((lane & 3) * 4);

  for (int fc = 0; fc < 8; fc++) {
    __syncthreads();   // previous window's A/x reads complete

    // ---- issue A: 9 taps x (hi,lo), 18 float4 per thread ----
    {
      const int kofs = fc * 16;
#pragma unroll
      for (int p = 0; p < 18; p++) {
        int i = p * 256 + tid;
        int tile = i >> 8;               // tap*2 + hl
        int rem = i & 255;
        int r = rem >> 1, ch = rem & 1;
        int tap = tile >> 1, hl = tile & 1;
        const __half* src = (hl ? kl : kh) + (size_t)r * 1152 + tap * 128 + kofs + ch * 8;
        uint32_t dst = (uint32_t)(tile * ATILE + r * 32 + ((ch << 4) ^ ((r & 4) << 2)));
        CPA16(sab + dst, src);
      }
      CPCOMMIT();
    }
    // ---- stage x tile (overlaps A cp.async) ----
    {
      const int fib = fc * 16;
#pragma unroll
      for (int p = 0; p < 17; p++) {
        int i = p * 256 + tid;
        int fi = i / 272, cell = i - fi * 272;
        int r = cell / 68, c = cell - r * 68;
        int gr = 2 * t + r;            // padded row
        float v = 0.f;
        if ((unsigned)(gr - 1) < (unsigned)HH && (unsigned)(c - 1) < (unsigned)WW)
          v = xb[(size_t)(fib + fi) * (HH * WW) + (gr - 1) * WW + (c - 1)];
        *reinterpret_cast<__half*>(sxt + cell * CS + fi * 2) = __float2half(v);
      }
    }
    CPWAIT0();
    __syncthreads();

    // ---- compute: 9 taps, no barriers ----
#pragma unroll
    for (int tap = 0; tap < 9; tap++) {
      const int off = (tap / 3) * 68 + (tap % 3);
      uint32_t bfr[8];
#pragma unroll
      for (int j = 0; j < 4; j++) {
        uint32_t ca = (uint32_t)((pj[j] + off) * CS) + bOff;
        bfr[2 * j]     = *reinterpret_cast<const uint32_t*>(sxt + ca);
        bfr[2 * j + 1] = *reinterpret_cast<const uint32_t*>(sxt + ca + 16);
      }
      const uint32_t tileH = sab + (uint32_t)(tap * 2 * ATILE) + aRowBase;
      uint32_t a[4][4];
#pragma unroll
      for (int f = 0; f < 4; f++)
        LDSM4(a[f][0], a[f][1], a[f][2], a[f][3], tileH + (uint32_t)(f * 512));
#pragma unroll
      for (int f = 0; f < 4; f++)
#pragma unroll
        for (int j = 0; j < 4; j++)
          MMA16816(acc[f][j], a[f], bfr[2 * j], bfr[2 * j + 1]);
#pragma unroll
      for (int f = 0; f < 4; f++)
        LDSM4(a[f][0], a[f][1], a[f][2], a[f][3], tileH + (uint32_t)(ATILE + f * 512));
#pragma unroll
      for (int f = 0; f < 4; f++)
#pragma unroll
        for (int j = 0; j < 4; j++)
          MMA16816(acc[f][j], a[f], bfr[2 * j], bfr[2 * j + 1]);
    }
  }

  // ---- epilogue: bias + store ----
  float* ob = out + (size_t)b * (NFOUT * HH * WW) + t * 128;
#pragma unroll
  for (int f = 0; f < 4; f++) {
    int fo0 = wm * 64 + f * 16 + (lane >> 2);
    float bv0 = sbias[fo0], bv1 = sbias[fo0 + 8];
#pragma unroll
    for (int j = 0; j < 4; j++) {
      int n = wn * 32 + j * 8 + 2 * (lane & 3);
      float2 v0 = make_float2(acc[f][j][0] + bv0, acc[f][j][1] + bv0);
      float2 v1 = make_float2(acc[f][j][2] + bv1, acc[f][j][3] + bv1);
      *reinterpret_cast<float2*>(ob + (size_t)fo0 * (HH * WW) + n) = v0;
      *reinterpret_cast<float2*>(ob + (size_t)(fo0 + 8) * (HH * WW) + n) = v1;
    }
  }
}

// ===========================================================================
extern "C" void kernel_launch(void* const* d_in, const int* in_sizes, int n_in,
                              void* d_out, int out_size) {
  const float* x   = (const float*)d_in[0];
  const float* lat = (const float*)d_in[1];
  const float* Wm  = (const float*)d_in[2];
  const float* bv  = (const float*)d_in[3];
  float* out = (float*)d_out;

  cudaFuncSetAttribute(hyper_gemm, cudaFuncAttributeMaxDynamicSharedMemorySize, HSMEM);
  cudaFuncSetAttribute(conv_mma, cudaFuncAttributeMaxDynamicSharedMemorySize, CONV_SMEM);

  hyper_gemm<<<(NROWS + 255) / 256, 256, HSMEM>>>(lat, Wm, bv);

  dim3 g(HH * WW / 128, NB);   // 32 x 16 = 512 CTAs
  conv_mma<<<g, 256, CONV_SMEM>>>(x, out);
}

// round 15
// speedup vs baseline: 1.3288x; 1.2165x over previous
#include <cuda_runtime.h>
#include <cuda_fp16.h>
#include <cstdint>

typedef unsigned long long ull;

#define NROWS 147584
#define KSIZE 147456
#define LATD  512
#define NB    16
#define NFIN  128
#define NFOUT 128
#define HH    64
#define WW    64

// single-fp16 weights, k-reordered: k' = tap*128 + fi
__device__ __align__(16) __half g_kh[NB * KSIZE];   // 4.72 MB
__device__ float g_bias[NB * NFOUT];

// ---------------- f32x2 helpers (hyper_gemm) ----------------
#define PK2(dst, a, b) \
  asm("mov.b64 %0, {%1, %2};" : "=l"(dst) : "r"(__float_as_uint(a)), "r"(__float_as_uint(b)))
#define FMA2(acc, a, b) \
  asm("fma.rn.f32x2 %0, %1, %2, %3;" : "=l"(acc) : "l"(a), "l"(b), "l"(acc))

// ---------------- cp.async ----------------
#define CPA16(dst, src) \
  asm volatile("cp.async.cg.shared.global [%0], [%1], 16;" :: "r"(dst), "l"(src))
#define CPCOMMIT() asm volatile("cp.async.commit_group;" ::: "memory")
#define CPWAIT1()  asm volatile("cp.async.wait_group 1;" ::: "memory")
#define CPWAIT0()  asm volatile("cp.async.wait_group 0;" ::: "memory")

__device__ __forceinline__ uint32_t smem_u32(const void* p) {
  uint32_t a;
  asm("{ .reg .u64 t; cvta.to.shared.u64 t, %1; cvt.u32.u64 %0, t; }" : "=r"(a) : "l"(p));
  return a;
}

// ---------------- warp-MMA helpers ----------------
#define LDSM4(r0, r1, r2, r3, addr) \
  asm volatile("ldmatrix.sync.aligned.m8n8.x4.shared.b16 {%0,%1,%2,%3}, [%4];" \
               : "=r"(r0), "=r"(r1), "=r"(r2), "=r"(r3) : "r"(addr))
#define MMA16816(c, a, b0, b1) \
  asm volatile("mma.sync.aligned.m16n8k16.row.col.f32.f16.f16.f32 " \
               "{%0,%1,%2,%3}, {%4,%5,%6,%7}, {%8,%9}, {%0,%1,%2,%3};" \
               : "+f"((c)[0]), "+f"((c)[1]), "+f"((c)[2]), "+f"((c)[3]) \
               : "r"((a)[0]), "r"((a)[1]), "r"((a)[2]), "r"((a)[3]), \
                 "r"(b0), "r"(b1))

// ===========================================================================
// Kernel A: hyper GEMM (R10 FFMA2 version, known 94us). 512 rows/block,
// 2 rows/thread, W staged via float4 cp.async double-buffered.
// Epilogue emits SINGLE fp16 weights in k' = tap*128+fi order + f32 bias.
// ===========================================================================
#define HKC   16
#define HRS   20                              // row stride (floats)
#define HROWS 512
#define HBUF  (HROWS * HRS)                   // floats per buffer
#define HSMEM ((2 * HBUF + LATD * 16) * 4)    // 81920 + 32768 = 114688 B

__global__ __launch_bounds__(256) void hyper_gemm(
    const float* __restrict__ lat, const float* __restrict__ Wm,
    const float* __restrict__ bias)
{
  extern __shared__ __align__(16) float hsm[];
  float* Ws = hsm;                     // [2][512][20]
  float* latc = hsm + 2 * HBUF;        // [512][16]
  const uint32_t wsb = smem_u32(Ws);
  const int tid = threadIdx.x;
  const int j0 = blockIdx.x * HROWS;

  ull acc[2][8];
#pragma unroll
  for (int r = 0; r < 2; r++)
#pragma unroll
    for (int i = 0; i < 8; i++) acc[r][i] = 0ull;

  for (int idx = tid; idx < LATD * 16; idx += 256)
    latc[idx] = lat[(idx & 15) * LATD + (idx >> 4)];

  // prologue: chunk 0 -> buf 0  (8 float4 per thread)
#pragma unroll
  for (int p = 0; p < 8; p++) {
    int idx = p * 256 + tid;
    int r = idx >> 2, q = idx & 3;
    if (j0 + r < NROWS)
      CPA16(wsb + (uint32_t)(r * HRS + q * 4) * 4,
            Wm + (size_t)(j0 + r) * LATD + q * 4);
  }
  CPCOMMIT();

  int buf = 0;
  for (int c = 0; c < LATD / HKC; c++) {
    if (c + 1 < LATD / HKC) {
#pragma unroll
      for (int p = 0; p < 8; p++) {
        int idx = p * 256 + tid;
        int r = idx >> 2, q = idx & 3;
        if (j0 + r < NROWS)
          CPA16(wsb + (uint32_t)((buf ^ 1) * HBUF + r * HRS + q * 4) * 4,
                Wm + (size_t)(j0 + r) * LATD + (c + 1) * HKC + q * 4);
      }
      CPCOMMIT();
      CPWAIT1();
    } else {
      CPWAIT0();
    }
    __syncthreads();

    const ulonglong2* latp = reinterpret_cast<const ulonglong2*>(latc);
    const float* wr0 = &Ws[buf * HBUF + tid * HRS];
    const float* wr1 = &Ws[buf * HBUF + (tid + 256) * HRS];
#pragma unroll
    for (int k = 0; k < HKC; k++) {
      float w0 = wr0[k], w1 = wr1[k];
      ull w20, w21; PK2(w20, w0, w0); PK2(w21, w1, w1);
      int kk = c * HKC + k;
#pragma unroll
      for (int q = 0; q < 4; q++) {
        ulonglong2 lv = latp[kk * 4 + q];
        FMA2(acc[0][2 * q + 0], w20, lv.x);
        FMA2(acc[0][2 * q + 1], w20, lv.y);
        FMA2(acc[1][2 * q + 0], w21, lv.x);
        FMA2(acc[1][2 * q + 1], w21, lv.y);
      }
    }
    buf ^= 1;
    __syncthreads();
  }

#pragma unroll
  for (int rr = 0; rr < 2; rr++) {
    int j = j0 + tid + rr * 256;
    if (j < KSIZE) {
      int fo = j / 1152;
      int rem = j - fo * 1152;
      int fi = rem / 9;
      int tap = rem - fi * 9;
      size_t dst = (size_t)fo * 1152 + tap * 128 + fi;
      float bv = bias[j];
#pragma unroll
      for (int p = 0; p < 8; p++) {
        float2 v = *reinterpret_cast<float2*>(&acc[rr][p]);
        g_kh[(size_t)(2 * p + 0) * KSIZE + dst] = __float2half(v.x + bv);
        g_kh[(size_t)(2 * p + 1) * KSIZE + dst] = __float2half(v.y + bv);
      }
    } else if (j < NROWS) {
      int fo = j - KSIZE;
      float bv = bias[j];
#pragma unroll
      for (int p = 0; p < 8; p++) {
        float2 v = *reinterpret_cast<float2*>(&acc[rr][p]);
        g_bias[(2 * p + 0) * NFOUT + fo] = v.x + bv;
        g_bias[(2 * p + 1) * NFOUT + fo] = v.y + bv;
      }
    }
  }
}

// ===========================================================================
// Kernel B: warp-MMA SINGLE-pass fp16 implicit-GEMM conv, window-level
// double buffering. CTA = (sample, 128-px tile). 8 warps M64xN32.
// Per fc-window (8 windows of 16 fi):
//   sync#1 (compute fc-1 done) -> issue A(fc+1) 9-tap tile (36.9KB) into
//   A-buf^1 via cp.async -> wait_group1 (A(fc) landed) -> sync#2 ->
//   stage x(fc+1) into x-buf^1 (overlaps compute warp-wise) ->
//   compute 9 taps x 16 MMA from A(fc), x(fc).
// A(fc+1) copy gets a full 144-MMA/warp window to land -> staging hidden.
// A rows XOR-swizzled 32B: off = r*32 + ((ch*16) ^ ((r&4)<<2)).
// ===========================================================================
#define CS    36                      // bytes per x cell (16 fp16 + 4 pad)
#define XTB   (272 * CS)              // 9792 B per x buffer
#define ATILE 4096                    // one tap tile: 128 rows * 32 B
#define AWIN  (9 * ATILE)             // 36864 B per window buffer
#define X_OFF (2 * AWIN)              // 73728
#define BIAS_OFF (X_OFF + 2 * XTB)    // 93312
#define CONV_SMEM (BIAS_OFF + NFOUT * 4)   // 93824 B

__device__ __forceinline__ void conv_issue_A(
    uint32_t sab, const __half* kh, int fc, int bufofs, int tid)
{
  const int kofs = fc * 16;
#pragma unroll
  for (int p = 0; p < 9; p++) {
    int i = p * 256 + tid;
    int tap = i >> 8;
    int rem = i & 255;
    int r = rem >> 1, ch = rem & 1;
    const __half* src = kh + (size_t)r * 1152 + tap * 128 + kofs + ch * 8;
    uint32_t dst = (uint32_t)(bufofs + tap * ATILE + r * 32 + ((ch << 4) ^ ((r & 4) << 2)));
    CPA16(sab + dst, src);
  }
  CPCOMMIT();
}

__device__ __forceinline__ void conv_stage_x(
    unsigned char* sxt, const float* xb, int fc, int t, int tid)
{
  const int fib = fc * 16;
#pragma unroll
  for (int p = 0; p < 17; p++) {
    int i = p * 256 + tid;
    int fi = i / 272, cell = i - fi * 272;
    int r = cell / 68, c = cell - r * 68;
    int gr = 2 * t + r;                // padded row
    float v = 0.f;
    if ((unsigned)(gr - 1) < (unsigned)HH && (unsigned)(c - 1) < (unsigned)WW)
      v = xb[(size_t)(fib + fi) * (HH * WW) + (gr - 1) * WW + (c - 1)];
    *reinterpret_cast<__half*>(sxt + cell * CS + fi * 2) = __float2half(v);
  }
}

__global__ __launch_bounds__(256, 2) void conv_mma(
    const float* __restrict__ x, float* __restrict__ out)
{
  extern __shared__ __align__(16) unsigned char sm[];
  float* sbias = reinterpret_cast<float*>(sm + BIAS_OFF);

  const int tid = threadIdx.x;
  const int lane = tid & 31, wid = tid >> 5;
  const int wm = wid >> 2;          // m-half (64 fouts)
  const int wn = wid & 3;           // n-quarter (32 px)
  const int t = blockIdx.x;         // out rows 2t, 2t+1
  const int b = blockIdx.y;

  float acc[4][4][4];
#pragma unroll
  for (int f = 0; f < 4; f++)
#pragma unroll
    for (int j = 0; j < 4; j++)
#pragma unroll
      for (int q = 0; q < 4; q++) acc[f][j][q] = 0.f;

  if (tid < NFOUT) sbias[tid] = g_bias[b * NFOUT + tid];

  const __half* kh = g_kh + (size_t)b * KSIZE;
  const float* xb = x + (size_t)(b * NFIN) * (HH * WW);

  const uint32_t sab = smem_u32(sm);
  const uint32_t aRowBase =
      (uint32_t)((wm * 64 + (lane & 15)) * 32) +
      ((uint32_t)((lane >> 4) << 4) ^ (uint32_t)((lane & 4) << 2));

  int pj[4];
#pragma unroll
  for (int j = 0; j < 4; j++) {
    int px = wn * 32 + j * 8 + (lane >> 2);
    pj[j] = (px >> 6) * 68 + (px & 63);
  }
  const uint32_t bOff = (uint32_t)((lane & 3) * 4);

  // prologue: x(0) and A(0)
  conv_stage_x(sm + X_OFF, xb, 0, t, tid);
  conv_issue_A(sab, kh, 0, 0, tid);

  for (int fc = 0; fc < 8; fc++) {
    __syncthreads();                 // compute(fc-1) done: A buf^1 + x buf^1 free
    if (fc + 1 < 8) {
      conv_issue_A(sab, kh, fc + 1, ((fc + 1) & 1) * AWIN, tid);
      CPWAIT1();                     // A(fc) landed; A(fc+1) in flight
    } else {
      CPWAIT0();
    }
    __syncthreads();                 // A(fc) + x(fc) visible to all warps

    // stage x(fc+1): overlaps this window's compute warp-wise
    if (fc + 1 < 8)
      conv_stage_x(sm + X_OFF + ((fc + 1) & 1) * XTB, xb, fc + 1, t, tid);

    unsigned char* sxt = sm + X_OFF + (fc & 1) * XTB;
    const uint32_t abase = sab + (uint32_t)((fc & 1) * AWIN) + aRowBase;
#pragma unroll
    for (int tap = 0; tap < 9; tap++) {
      const int off = (tap / 3) * 68 + (tap % 3);
      uint32_t bfr[8];
#pragma unroll
      for (int j = 0; j < 4; j++) {
        uint32_t ca = (uint32_t)((pj[j] + off) * CS) + bOff;
        bfr[2 * j]     = *reinterpret_cast<const uint32_t*>(sxt + ca);
        bfr[2 * j + 1] = *reinterpret_cast<const uint32_t*>(sxt + ca + 16);
      }
      const uint32_t tileH = abase + (uint32_t)(tap * ATILE);
      uint32_t a[4][4];
#pragma unroll
      for (int f = 0; f < 4; f++)
        LDSM4(a[f][0], a[f][1], a[f][2], a[f][3], tileH + (uint32_t)(f * 512));
#pragma unroll
      for (int f = 0; f < 4; f++)
#pragma unroll
        for (int j = 0; j < 4; j++)
          MMA16816(acc[f][j], a[f], bfr[2 * j], bfr[2 * j + 1]);
    }
  }

  // ---- epilogue: bias + store ----
  float* ob = out + (size_t)b * (NFOUT * HH * WW) + t * 128;
#pragma unroll
  for (int f = 0; f < 4; f++) {
    int fo0 = wm * 64 + f * 16 + (lane >> 2);
    float bv0 = sbias[fo0], bv1 = sbias[fo0 + 8];
#pragma unroll
    for (int j = 0; j < 4; j++) {
      int n = wn * 32 + j * 8 + 2 * (lane & 3);
      float2 v0 = make_float2(acc[f][j][0] + bv0, acc[f][j][1] + bv0);
      float2 v1 = make_float2(acc[f][j][2] + bv1, acc[f][j][3] + bv1);
      *reinterpret_cast<float2*>(ob + (size_t)fo0 * (HH * WW) + n) = v0;
      *reinterpret_cast<float2*>(ob + (size_t)(fo0 + 8) * (HH * WW) + n) = v1;
    }
  }
}

// ===========================================================================
extern "C" void kernel_launch(void* const* d_in, const int* in_sizes, int n_in,
                              void* d_out, int out_size) {
  const float* x   = (const float*)d_in[0];
  const float* lat = (const float*)d_in[1];
  const float* Wm  = (const float*)d_in[2];
  const float* bv  = (const float*)d_in[3];
  float* out = (float*)d_out;

  cudaFuncSetAttribute(hyper_gemm, cudaFuncAttributeMaxDynamicSharedMemorySize, HSMEM);
  cudaFuncSetAttribute(conv_mma, cudaFuncAttributeMaxDynamicSharedMemorySize, CONV_SMEM);

  hyper_gemm<<<(NROWS + HROWS - 1) / HROWS, 256, HSMEM>>>(lat, Wm, bv);

  dim3 g(HH * WW / 128, NB);   // 32 x 16 = 512 CTAs
  conv_mma<<<g, 256, CONV_SMEM>>>(x, out);
}